// round 5
// baseline (speedup 1.0000x reference)
#include <cuda_runtime.h>
#include <cstdint>
#include <math.h>

#define N_TOK   8192
#define D_DIM   4096
#define E_NUM   8
#define R_RANK  128
#define SCALING 0.25f
#define MT      64

__device__ int   g_cnt[2][E_NUM];
__device__ int   g_tok[2][E_NUM][N_TOK];
__device__ float g_wt [2][E_NUM][N_TOK];
// tf32-preconverted operands (stored as f32 bit patterns with low mantissa zeroed)
__device__ float g_xt[(size_t)N_TOK * D_DIM];            // 128 MB
__device__ float g_at[(size_t)E_NUM * R_RANK * D_DIM];   // 16 MB
__device__ float g_bt[(size_t)E_NUM * D_DIM * R_RANK];   // 16 MB

// ---- dynamic smem layout (bytes) ----
#define SZ_H        (64 * 132 * 4)                  // 33792: H tile [64][132w]
#define OFF_S1X(b)  (SZ_H + (b) * 17408)            // X tile [64][68w]  x2
#define OFF_S1A(b)  (SZ_H + 34816 + (b) * 34816)    // A tile [128][68w] x2
#define OFF_S2B(b)  (SZ_H + (b) * 67584)            // B chunk [128][132w] x2
#define SMEM_BYTES  (SZ_H + 2 * 67584)              // 168960

__device__ __forceinline__ uint32_t smem_u32(const void* p) {
    uint32_t a;
    asm("{ .reg .u64 t; cvta.to.shared.u64 t, %1; cvt.u32.u64 %0, t; }" : "=r"(a) : "l"(p));
    return a;
}
__device__ __forceinline__ uint32_t cvt_tf32(float f) {
    uint32_t r; asm("cvt.rna.tf32.f32 %0, %1;" : "=r"(r) : "f"(f)); return r;
}
__device__ __forceinline__ float tf32f(float f) { return __uint_as_float(cvt_tf32(f)); }

#define CP16(sa, gp) asm volatile("cp.async.cg.shared.global [%0], [%1], 16;" :: "r"(sa), "l"(gp))
#define CPCOMMIT()   asm volatile("cp.async.commit_group;" ::: "memory")
#define CPWAIT(n)    asm volatile("cp.async.wait_group %0;" :: "n"(n) : "memory")

__device__ __forceinline__ void mma8(float* c, const uint32_t* a, const uint32_t* b) {
    asm volatile("mma.sync.aligned.m16n8k8.row.col.f32.tf32.tf32.f32 "
        "{%0,%1,%2,%3}, {%4,%5,%6,%7}, {%8,%9}, {%0,%1,%2,%3};"
        : "+f"(c[0]), "+f"(c[1]), "+f"(c[2]), "+f"(c[3])
        : "r"(a[0]), "r"(a[1]), "r"(a[2]), "r"(a[3]), "r"(b[0]), "r"(b[1]));
}

// ---------------- kernels ----------------
__global__ void reset_kernel() {
    if (threadIdx.x < 2 * E_NUM) ((int*)g_cnt)[threadIdx.x] = 0;
}

// Convert A and B to tf32 (1 element of each per thread).
__global__ __launch_bounds__(256) void cvt_wt(const float4* __restrict__ A,
                                              const float4* __restrict__ B)
{
    size_t i = (size_t)blockIdx.x * blockDim.x + threadIdx.x;
    const size_t n4 = (size_t)E_NUM * R_RANK * D_DIM / 4;
    if (i >= n4) return;
    float4 a = A[i], b = B[i];
    ((float4*)g_at)[i] = make_float4(tf32f(a.x), tf32f(a.y), tf32f(a.z), tf32f(a.w));
    ((float4*)g_bt)[i] = make_float4(tf32f(b.x), tf32f(b.y), tf32f(b.z), tf32f(b.w));
}

// Router: logits, top-2, slot-separated lists. Also writes the tf32 copy of x.
__global__ __launch_bounds__(256) void router_kernel(
    const float* __restrict__ x, const float* __restrict__ Wr, const float* __restrict__ br)
{
    const int n = blockIdx.x, tid = threadIdx.x;
    const float* xr = x + (size_t)n * D_DIM;
    float* xw = g_xt + (size_t)n * D_DIM;
    float acc[E_NUM];
#pragma unroll
    for (int e = 0; e < E_NUM; e++) acc[e] = 0.f;
    for (int d = tid * 4; d < D_DIM; d += 1024) {
        float4 xv = *(const float4*)(xr + d);
        *(float4*)(xw + d) = make_float4(tf32f(xv.x), tf32f(xv.y), tf32f(xv.z), tf32f(xv.w));
#pragma unroll
        for (int e = 0; e < E_NUM; e++) {
            float4 wv = *(const float4*)(Wr + (size_t)e * D_DIM + d);
            acc[e] += xv.x*wv.x + xv.y*wv.y + xv.z*wv.z + xv.w*wv.w;
        }
    }
#pragma unroll
    for (int e = 0; e < E_NUM; e++)
#pragma unroll
        for (int off = 16; off > 0; off >>= 1)
            acc[e] += __shfl_xor_sync(0xffffffffu, acc[e], off);
    __shared__ float sm[E_NUM][8];
    const int warp = tid >> 5, lane = tid & 31;
    if (lane == 0)
#pragma unroll
        for (int e = 0; e < E_NUM; e++) sm[e][warp] = acc[e];
    __syncthreads();
    if (tid == 0) {
        float lg[E_NUM];
#pragma unroll
        for (int e = 0; e < E_NUM; e++) {
            float s = 0.f;
#pragma unroll
            for (int w = 0; w < 8; w++) s += sm[e][w];
            lg[e] = s + br[e];
        }
        int i0 = 0;
#pragma unroll
        for (int e = 1; e < E_NUM; e++) if (lg[e] > lg[i0]) i0 = e;
        int i1 = (i0 == 0) ? 1 : 0;
#pragma unroll
        for (int e = 0; e < E_NUM; e++) if (e != i0 && lg[e] > lg[i1]) i1 = e;
        float e1  = expf(lg[i1] - lg[i0]);
        float inv = SCALING / (1.f + e1);
        int p0 = atomicAdd(&g_cnt[0][i0], 1);
        g_tok[0][i0][p0] = n;  g_wt[0][i0][p0] = inv;
        int p1 = atomicAdd(&g_cnt[1][i1], 1);
        g_tok[1][i1][p1] = n;  g_wt[1][i1][p1] = e1 * inv;
    }
}

__global__ __launch_bounds__(256, 1)
void expert_kernel(float* __restrict__ out, int slot)
{
    const int e    = blockIdx.y;
    const int cnt  = g_cnt[slot][e];
    const int base = blockIdx.x * MT;
    if (base >= cnt) return;

    extern __shared__ char dsm[];
    __shared__ int   stok[MT];
    __shared__ float swt[MT];

    const int tid  = threadIdx.x;
    const int lane = tid & 31, warp = tid >> 5;
    const int wm = warp >> 2, wn = warp & 3;     // warp grid 2m x 4n
    const int lm = lane >> 2, lk = lane & 3;

    if (tid < MT) {
        int p = base + tid;
        if (p < cnt) { stok[tid] = g_tok[slot][e][p];    swt[tid] = g_wt[slot][e][p]; }
        else         { stok[tid] = g_tok[slot][e][base]; swt[tid] = 0.f;              }
    }
    __syncthreads();

    const uint32_t sb = smem_u32(dsm);

    // ---- cp.async plumbing ----
    // Stage1 X (KB=64): 4 chunks/thread: row = tid>>2, chunk16 = (tid&3)+4j
    const int xr_ = tid >> 2, xc_ = tid & 3;
    const float* xg = g_xt + (size_t)stok[xr_] * D_DIM + xc_ * 4;
    const uint32_t xo = (uint32_t)xr_ * 272u + (uint32_t)xc_ * 16u;
    // Stage1 A (KB=64): 8 chunks/thread: row = tid>>1, chunk16 = (tid&1)+2j
    const int ar_ = tid >> 1, ac_ = tid & 1;
    const float* ag = g_at + ((size_t)e * R_RANK + ar_) * D_DIM + ac_ * 4;
    const uint32_t ao = (uint32_t)ar_ * 272u + (uint32_t)ac_ * 16u;
    // Stage2 B: 16 chunks/thread: rows warp+8j, chunk16 = lane
    const float* bg = g_bt + (size_t)e * D_DIM * R_RANK + (size_t)warp * R_RANK + lane * 4;
    const uint32_t bo = (uint32_t)warp * 528u + (uint32_t)lane * 16u;

    float c[2][4][4];
#pragma unroll
    for (int mt = 0; mt < 2; mt++)
#pragma unroll
        for (int nt = 0; nt < 4; nt++)
#pragma unroll
            for (int q = 0; q < 4; q++) c[mt][nt][q] = 0.f;

    // ================= stage 1: h = X_g @ A_e^T  (K=4096, 64 tiles of 64) ===
    {
#pragma unroll
        for (int j = 0; j < 4; j++) CP16(sb + OFF_S1X(0) + xo + j * 64u, xg + j * 16);
#pragma unroll
        for (int j = 0; j < 8; j++) CP16(sb + OFF_S1A(0) + ao + j * 32u, ag + j * 8);
        CPCOMMIT();
    }
    for (int kt = 0; kt < 64; kt++) {
        if (kt + 1 < 64) {
            const int b = (kt + 1) & 1, gk = (kt + 1) * 64;
#pragma unroll
            for (int j = 0; j < 4; j++) CP16(sb + OFF_S1X(b) + xo + j * 64u, xg + gk + j * 16);
#pragma unroll
            for (int j = 0; j < 8; j++) CP16(sb + OFF_S1A(b) + ao + j * 32u, ag + gk + j * 8);
            CPCOMMIT();
            CPWAIT(1);
        } else {
            CPWAIT(0);
        }
        __syncthreads();
        const uint32_t* Xs = (const uint32_t*)(dsm + OFF_S1X(kt & 1));
        const uint32_t* As = (const uint32_t*)(dsm + OFF_S1A(kt & 1));
#pragma unroll
        for (int ks = 0; ks < 8; ks++) {
            const int k0 = ks * 8 + lk;
            uint32_t af[2][4], bf[4][2];
#pragma unroll
            for (int mt = 0; mt < 2; mt++) {
                const int r0 = wm * 32 + mt * 16 + lm;
                af[mt][0] = Xs[r0 * 68 + k0];
                af[mt][1] = Xs[(r0 + 8) * 68 + k0];
                af[mt][2] = Xs[r0 * 68 + k0 + 4];
                af[mt][3] = Xs[(r0 + 8) * 68 + k0 + 4];
            }
#pragma unroll
            for (int nt = 0; nt < 4; nt++) {
                const int n0 = wn * 32 + nt * 8 + lm;
                bf[nt][0] = As[n0 * 68 + k0];
                bf[nt][1] = As[n0 * 68 + k0 + 4];
            }
#pragma unroll
            for (int mt = 0; mt < 2; mt++)
#pragma unroll
                for (int nt = 0; nt < 4; nt++) mma8(c[mt][nt], af[mt], bf[nt]);
        }
        __syncthreads();
    }

    // ---- stage2 chunk0 prefetch (S1 buffers now dead) ----
    {
        CPWAIT(0);
#pragma unroll
        for (int j = 0; j < 16; j++)
            CP16(sb + OFF_S2B(0) + bo + j * 4224u, bg + (size_t)j * 8 * R_RANK);
        CPCOMMIT();
    }

    // ---- H epilogue: gate-weight + tf32 -> smem ----
    uint32_t* Hs = (uint32_t*)dsm;
    int   tk[2][2]; float ww[2][2]; bool vv[2][2];
#pragma unroll
    for (int mt = 0; mt < 2; mt++)
#pragma unroll
        for (int h = 0; h < 2; h++) {
            const int r = wm * 32 + mt * 16 + lm + h * 8;
            tk[mt][h] = stok[r]; ww[mt][h] = swt[r]; vv[mt][h] = (base + r) < cnt;
        }
#pragma unroll
    for (int mt = 0; mt < 2; mt++)
#pragma unroll
        for (int h = 0; h < 2; h++) {
            const int r = wm * 32 + mt * 16 + lm + h * 8;
#pragma unroll
            for (int nt = 0; nt < 4; nt++) {
                const int col = wn * 32 + nt * 8 + lk * 2;
                uint2 v;
                v.x = cvt_tf32(c[mt][nt][h * 2]     * ww[mt][h]);
                v.y = cvt_tf32(c[mt][nt][h * 2 + 1] * ww[mt][h]);
                *(uint2*)&Hs[r * 132 + col] = v;
            }
        }
    __syncthreads();

    // ================= stage 2: out (+)= H @ B_e^T (32 chunks of N=128) =====
    for (int ch = 0; ch < 32; ch++) {
        if (ch + 1 < 32) {
            const int b = (ch + 1) & 1;
            const float* gp = bg + (size_t)(ch + 1) * 128 * R_RANK;
#pragma unroll
            for (int j = 0; j < 16; j++)
                CP16(sb + OFF_S2B(b) + bo + j * 4224u, gp + (size_t)j * 8 * R_RANK);
            CPCOMMIT();
            CPWAIT(1);
        } else {
            CPWAIT(0);
        }
        __syncthreads();
#pragma unroll
        for (int mt = 0; mt < 2; mt++)
#pragma unroll
            for (int nt = 0; nt < 4; nt++)
#pragma unroll
                for (int q = 0; q < 4; q++) c[mt][nt][q] = 0.f;

        const uint32_t* Bs = (const uint32_t*)(dsm + OFF_S2B(ch & 1));
#pragma unroll
        for (int ks = 0; ks < 16; ks++) {
            const int k0 = ks * 8 + lk;
            uint32_t af[2][4], bf[4][2];
#pragma unroll
            for (int mt = 0; mt < 2; mt++) {
                const int r0 = wm * 32 + mt * 16 + lm;
                af[mt][0] = Hs[r0 * 132 + k0];
                af[mt][1] = Hs[(r0 + 8) * 132 + k0];
                af[mt][2] = Hs[r0 * 132 + k0 + 4];
                af[mt][3] = Hs[(r0 + 8) * 132 + k0 + 4];
            }
#pragma unroll
            for (int nt = 0; nt < 4; nt++) {
                const int n0 = wn * 32 + nt * 8 + lm;
                bf[nt][0] = Bs[n0 * 132 + k0];
                bf[nt][1] = Bs[n0 * 132 + k0 + 4];
            }
#pragma unroll
            for (int mt = 0; mt < 2; mt++)
#pragma unroll
                for (int nt = 0; nt < 4; nt++) mma8(c[mt][nt], af[mt], bf[nt]);
        }
        const int d0 = ch * 128;
#pragma unroll
        for (int mt = 0; mt < 2; mt++)
#pragma unroll
            for (int h = 0; h < 2; h++) {
                if (!vv[mt][h]) continue;
                float* op = out + (size_t)tk[mt][h] * D_DIM + d0 + wn * 32 + lk * 2;
                if (slot == 0) {
#pragma unroll
                    for (int nt = 0; nt < 4; nt++)
                        *(float2*)(op + nt * 8) =
                            make_float2(c[mt][nt][h * 2], c[mt][nt][h * 2 + 1]);
                } else {
#pragma unroll
                    for (int nt = 0; nt < 4; nt++) {
                        float2 o = *(const float2*)(op + nt * 8);
                        o.x += c[mt][nt][h * 2];
                        o.y += c[mt][nt][h * 2 + 1];
                        *(float2*)(op + nt * 8) = o;
                    }
                }
            }
        __syncthreads();
    }
}

extern "C" void kernel_launch(void* const* d_in, const int* in_sizes, int n_in,
                              void* d_out, int out_size)
{
    (void)in_sizes; (void)n_in; (void)out_size;
    const float* x  = (const float*)d_in[0];
    const float* Wr = (const float*)d_in[1];
    const float* br = (const float*)d_in[2];
    const float* A  = (const float*)d_in[3];
    const float* B  = (const float*)d_in[4];
    float* out = (float*)d_out;

    cudaFuncSetAttribute(expert_kernel, cudaFuncAttributeMaxDynamicSharedMemorySize, SMEM_BYTES);
    reset_kernel<<<1, 32>>>();
    cvt_wt<<<(E_NUM * R_RANK * D_DIM / 4 + 255) / 256, 256>>>((const float4*)A, (const float4*)B);
    router_kernel<<<N_TOK, 256>>>(x, Wr, br);
    dim3 grid(N_TOK / MT, E_NUM);
    expert_kernel<<<grid, 256, SMEM_BYTES>>>(out, 0);
    expert_kernel<<<grid, 256, SMEM_BYTES>>>(out, 1);
}